// round 1
// baseline (speedup 1.0000x reference)
#include <cuda_runtime.h>
#include <cuda_bf16.h>
#include <mma.h>

using namespace nvcuda;

// ---------------- problem constants ----------------
#define BATCH   16
#define DIM     256
#define HEADS   8
#define DHEAD   32
#define INNER   256          // HEADS*DHEAD
#define NPIX    4096         // 64*64
#define SCALE   0.17677669529663687f   // 32^-0.5
#define EPS     1e-5f

// ---------------- scratch (device globals; no allocation allowed) --------
__device__ float g_xn [(size_t)BATCH * DIM   * NPIX];   // 64 MB: LN(x), later attn output
__device__ float g_b1 [(size_t)BATCH * 768   * NPIX];   // 192 MB: qkv after 1x1; later y
__device__ float g_b2 [(size_t)BATCH * 768   * NPIX];   // 192 MB: qkv after dwconv
__device__ float g_ctx[(size_t)BATCH * HEADS * DHEAD * DHEAD];

// =====================================================================
// 1/9. channel LayerNorm: out[b,c,p] = (x - mean_c)/sqrt(var_c+eps) * g[c]
// =====================================================================
__global__ __launch_bounds__(256)
void ln_kernel(const float* __restrict__ in, const float* __restrict__ g,
               float* __restrict__ out)
{
    int idx = blockIdx.x * 256 + threadIdx.x;          // (b,p) over 16*4096
    int b = idx >> 12, p = idx & 4095;
    const float* base = in  + (size_t)b * DIM * NPIX + p;
    float*       ob   = out + (size_t)b * DIM * NPIX + p;

    float s = 0.f, ss = 0.f;
#pragma unroll 8
    for (int c = 0; c < DIM; c++) {
        float v = base[(size_t)c * NPIX];
        s += v; ss += v * v;
    }
    float mean = s * (1.f / DIM);
    float var  = ss * (1.f / DIM) - mean * mean;
    float rstd = rsqrtf(var + EPS);
#pragma unroll 8
    for (int c = 0; c < DIM; c++) {
        ob[(size_t)c * NPIX] = (base[(size_t)c * NPIX] - mean) * rstd * g[c];
    }
}

// =====================================================================
// 2/9, 8/9. tf32 WMMA GEMM:  C[b,o,p] = sum_c A[o,c] * B[b,c,p]
//   A: [256,256] row-major (1x1 conv weight),  B: [K=256, N=4096] ld=4096
//   Block tile 128x64, BK=32, 8 warps (4x2), each warp 32x32 (2x2 frags)
// =====================================================================
#define GBM 128
#define GBN 64
#define GBK 32

__global__ __launch_bounds__(256)
void gemm_tf32(const float* __restrict__ A, const float* __restrict__ B,
               float* __restrict__ C, long strideB, long strideC)
{
    __shared__ float As[GBM][GBK + 4];   // ld 36
    __shared__ float Bs[GBK][GBN + 4];   // ld 68

    const float* Bb = B + (size_t)blockIdx.z * strideB;
    float*       Cb = C + (size_t)blockIdx.z * strideC;

    int tid = threadIdx.x;
    int warp = tid >> 5;
    int wm = warp >> 1;        // 0..3
    int wn = warp & 1;         // 0..1
    int bm = blockIdx.y * GBM;
    int bn = blockIdx.x * GBN;

    wmma::fragment<wmma::accumulator, 16, 16, 8, float> acc[2][2];
#pragma unroll
    for (int i = 0; i < 2; i++)
#pragma unroll
        for (int j = 0; j < 2; j++) wmma::fill_fragment(acc[i][j], 0.f);

    int ar = tid >> 3;                 // 0..31
    int ac = (tid & 7) * 4;            // 0..28

    for (int kt = 0; kt < 256; kt += GBK) {
        // load A tile 128x32 (float4, convert to tf32)
#pragma unroll
        for (int i = 0; i < 4; i++) {
            int row = ar + i * 32;
            float4 v = *(const float4*)(&A[(size_t)(bm + row) * 256 + kt + ac]);
            As[row][ac + 0] = wmma::__float_to_tf32(v.x);
            As[row][ac + 1] = wmma::__float_to_tf32(v.y);
            As[row][ac + 2] = wmma::__float_to_tf32(v.z);
            As[row][ac + 3] = wmma::__float_to_tf32(v.w);
        }
        // load B tile 32x64
#pragma unroll
        for (int i = 0; i < 2; i++) {
            int col = ac + i * 32;
            float4 v = *(const float4*)(&Bb[(size_t)(kt + ar) * NPIX + bn + col]);
            Bs[ar][col + 0] = wmma::__float_to_tf32(v.x);
            Bs[ar][col + 1] = wmma::__float_to_tf32(v.y);
            Bs[ar][col + 2] = wmma::__float_to_tf32(v.z);
            Bs[ar][col + 3] = wmma::__float_to_tf32(v.w);
        }
        __syncthreads();

#pragma unroll
        for (int kk = 0; kk < GBK; kk += 8) {
            wmma::fragment<wmma::matrix_a, 16, 16, 8, wmma::precision::tf32, wmma::row_major> af[2];
            wmma::fragment<wmma::matrix_b, 16, 16, 8, wmma::precision::tf32, wmma::row_major> bf[2];
#pragma unroll
            for (int i = 0; i < 2; i++)
                wmma::load_matrix_sync(af[i], &As[wm * 32 + i * 16][kk], GBK + 4);
#pragma unroll
            for (int j = 0; j < 2; j++)
                wmma::load_matrix_sync(bf[j], &Bs[kk][wn * 32 + j * 16], GBN + 4);
#pragma unroll
            for (int i = 0; i < 2; i++)
#pragma unroll
                for (int j = 0; j < 2; j++)
                    wmma::mma_sync(acc[i][j], af[i], bf[j], acc[i][j]);
        }
        __syncthreads();
    }

#pragma unroll
    for (int i = 0; i < 2; i++)
#pragma unroll
        for (int j = 0; j < 2; j++) {
            float* cp = Cb + (size_t)(bm + wm * 32 + i * 16) * NPIX + bn + wn * 32 + j * 16;
            wmma::store_matrix_sync(cp, acc[i][j], NPIX, wmma::mem_row_major);
        }
}

// =====================================================================
// 3/9. depthwise 3x3 conv, SAME pad. in/out: [b][768][64][64]
//   channels 0-255: wq_dw, 256-511: wk_dw, 512-767: wv_dw
// =====================================================================
__global__ __launch_bounds__(256)
void dwconv_kernel(const float* __restrict__ in,
                   const float* __restrict__ wq, const float* __restrict__ wk,
                   const float* __restrict__ wv, float* __restrict__ out)
{
    __shared__ float s[66 * 66];
    int bc = blockIdx.x;                // b*768 + ch
    int ch = bc % 768;
    const float* w9 = (ch < 256) ? wq + ch * 9
                     : (ch < 512) ? wk + (ch - 256) * 9
                                  : wv + (ch - 512) * 9;
    float w0 = w9[0], w1 = w9[1], w2 = w9[2], w3 = w9[3], w4 = w9[4],
          w5 = w9[5], w6 = w9[6], w7 = w9[7], w8 = w9[8];

    const float* ip = in  + (size_t)bc * NPIX;
    float*       op = out + (size_t)bc * NPIX;

    for (int i = threadIdx.x; i < 66 * 66; i += 256) s[i] = 0.f;
    __syncthreads();
    for (int i = threadIdx.x; i < NPIX; i += 256) {
        int x = i >> 6, y = i & 63;
        s[(x + 1) * 66 + y + 1] = ip[i];
    }
    __syncthreads();
    for (int i = threadIdx.x; i < NPIX; i += 256) {
        int x = i >> 6, y = i & 63;
        const float* c = &s[(x + 1) * 66 + (y + 1)];
        float r = c[-67] * w0 + c[-66] * w1 + c[-65] * w2
                + c[-1]  * w3 + c[0]   * w4 + c[1]   * w5
                + c[65]  * w6 + c[66]  * w7 + c[67]  * w8;
        op[i] = r;
    }
}

// =====================================================================
// 4/9. q softmax over the 32 feature channels of each head, then * SCALE
//   in-place on g_b2 channels [0,256)
// =====================================================================
__global__ __launch_bounds__(256)
void softmax_q_kernel(float* __restrict__ q)
{
    int idx = blockIdx.x * 256 + threadIdx.x;   // over 16*8*4096
    int p = idx & 4095;
    int bh = idx >> 12;
    int b = bh >> 3, h = bh & 7;
    float* base = q + ((size_t)b * 768 + h * DHEAD) * NPIX + p;

    float v[DHEAD];
    float m = -1e30f;
#pragma unroll
    for (int d = 0; d < DHEAD; d++) { v[d] = base[(size_t)d * NPIX]; m = fmaxf(m, v[d]); }
    float s = 0.f;
#pragma unroll
    for (int d = 0; d < DHEAD; d++) { v[d] = __expf(v[d] - m); s += v[d]; }
    float inv = SCALE / s;
#pragma unroll
    for (int d = 0; d < DHEAD; d++) base[(size_t)d * NPIX] = v[d] * inv;
}

// =====================================================================
// 5/9. k softmax over the 4096 sequence positions of each channel.
//   in-place on g_b2 channels [256,512). One block per (b, chan).
// =====================================================================
__global__ __launch_bounds__(256)
void softmax_k_kernel(float* __restrict__ kbuf)
{
    __shared__ float sh[8];
    int b = blockIdx.x >> 8;
    int c = blockIdx.x & 255;
    float* row = kbuf + ((size_t)b * 768 + 256 + c) * NPIX;
    int tid = threadIdx.x;

    float v[16];
    float m = -1e30f;
#pragma unroll
    for (int i = 0; i < 16; i++) { v[i] = row[tid + i * 256]; m = fmaxf(m, v[i]); }
#pragma unroll
    for (int o = 16; o; o >>= 1) m = fmaxf(m, __shfl_xor_sync(~0u, m, o));
    if ((tid & 31) == 0) sh[tid >> 5] = m;
    __syncthreads();
    m = sh[0];
#pragma unroll
    for (int w = 1; w < 8; w++) m = fmaxf(m, sh[w]);

    float s = 0.f;
#pragma unroll
    for (int i = 0; i < 16; i++) { v[i] = __expf(v[i] - m); s += v[i]; }
#pragma unroll
    for (int o = 16; o; o >>= 1) s += __shfl_xor_sync(~0u, s, o);
    __syncthreads();
    if ((tid & 31) == 0) sh[tid >> 5] = s;
    __syncthreads();
    s = 0.f;
#pragma unroll
    for (int w = 0; w < 8; w++) s += sh[w];

    float inv = 1.f / s;
#pragma unroll
    for (int i = 0; i < 16; i++) row[tid + i * 256] = v[i] * inv;
}

// =====================================================================
// 6/9. ctx[b,h,d,e] = sum_p k[b,h,p,d] * v[b,h,p,e].  One block per (b,h).
//   4 p-subgroups x (8x8 threads), each thread owns a 4x4 (d,e) tile.
// =====================================================================
__global__ __launch_bounds__(256)
void ctx_kernel(const float* __restrict__ b2, float* __restrict__ ctx)
{
    __shared__ float sh[8448];            // ksT[128][33] | vsT[128][33]
    float* ksT = sh;
    float* vsT = sh + 4224;

    int bh = blockIdx.x;                  // b*8 + h
    int b = bh >> 3, h = bh & 7;
    const float* kb = b2 + ((size_t)b * 768 + 256 + h * DHEAD) * NPIX;
    const float* vb = b2 + ((size_t)b * 768 + 512 + h * DHEAD) * NPIX;

    int tid = threadIdx.x;
    int pg = tid >> 6;                    // 0..3
    int t  = tid & 63;
    int d0 = (t >> 3) * 4;
    int e0 = (t & 7) * 4;

    float acc[16];
#pragma unroll
    for (int i = 0; i < 16; i++) acc[i] = 0.f;

    for (int c0 = 0; c0 < NPIX; c0 += 128) {
        __syncthreads();
        for (int i = tid; i < 4096; i += 256) {
            int d = i >> 7, p = i & 127;
            ksT[p * 33 + d] = kb[(size_t)d * NPIX + c0 + p];
            vsT[p * 33 + d] = vb[(size_t)d * NPIX + c0 + p];
        }
        __syncthreads();
        int pbeg = pg * 32;
#pragma unroll 4
        for (int pp = pbeg; pp < pbeg + 32; pp++) {
            float kk[4], vv[4];
#pragma unroll
            for (int i = 0; i < 4; i++) kk[i] = ksT[pp * 33 + d0 + i];
#pragma unroll
            for (int j = 0; j < 4; j++) vv[j] = vsT[pp * 33 + e0 + j];
#pragma unroll
            for (int i = 0; i < 4; i++)
#pragma unroll
                for (int j = 0; j < 4; j++) acc[i * 4 + j] += kk[i] * vv[j];
        }
    }
    __syncthreads();

    // reduce across the 4 p-subgroups through shared
    float* red = sh;                      // 4 * 1024 floats
#pragma unroll
    for (int i = 0; i < 4; i++)
#pragma unroll
        for (int j = 0; j < 4; j++)
            red[pg * 1024 + (d0 + i) * 32 + (e0 + j)] = acc[i * 4 + j];
    __syncthreads();

    float* cout = ctx + (size_t)bh * 1024;
    for (int i = tid; i < 1024; i += 256)
        cout[i] = red[i] + red[1024 + i] + red[2048 + i] + red[3072 + i];
}

// =====================================================================
// 7/9. out[b, h*32+e, p] = silu( sum_d q[b,h*32+d,p] * ctx[b,h,d,e] )
// =====================================================================
__global__ __launch_bounds__(256)
void attn_out_kernel(const float* __restrict__ qbuf, const float* __restrict__ ctx,
                     float* __restrict__ out)
{
    __shared__ float cs[DHEAD][DHEAD + 1];
    int blk = blockIdx.x;                 // (b*8+h)*16 + ptile
    int pt = blk & 15;
    int bh = blk >> 4;
    int b = bh >> 3, h = bh & 7;

    const float* cbase = ctx + (size_t)bh * 1024;
    for (int i = threadIdx.x; i < 1024; i += 256)
        cs[i >> 5][i & 31] = cbase[i];
    __syncthreads();

    int p = pt * 256 + threadIdx.x;
    const float* qb = qbuf + ((size_t)b * 768 + h * DHEAD) * NPIX + p;

    float qv[DHEAD];
#pragma unroll
    for (int d = 0; d < DHEAD; d++) qv[d] = qb[(size_t)d * NPIX];

    float o[DHEAD];
#pragma unroll
    for (int e = 0; e < DHEAD; e++) o[e] = 0.f;

#pragma unroll 8
    for (int d = 0; d < DHEAD; d++) {
        float qd = qv[d];
#pragma unroll
        for (int e = 0; e < DHEAD; e++) o[e] += qd * cs[d][e];
    }

    float* ob = out + ((size_t)b * DIM + h * DHEAD) * NPIX + p;
#pragma unroll
    for (int e = 0; e < DHEAD; e++) {
        float x = o[e];
        ob[(size_t)e * NPIX] = x / (1.f + __expf(-x));   // SiLU
    }
}

// =====================================================================
// launch
// =====================================================================
extern "C" void kernel_launch(void* const* d_in, const int* in_sizes, int n_in,
                              void* d_out, int out_size)
{
    const float* fmap   = (const float*)d_in[0];
    const float* gn     = (const float*)d_in[1];
    const float* wq1    = (const float*)d_in[2];
    const float* wq_dw  = (const float*)d_in[3];
    const float* wk1    = (const float*)d_in[4];
    const float* wk_dw  = (const float*)d_in[5];
    const float* wv1    = (const float*)d_in[6];
    const float* wv_dw  = (const float*)d_in[7];
    const float* wo     = (const float*)d_in[8];
    const float* gout   = (const float*)d_in[9];
    float* out = (float*)d_out;

    float *xn, *b1, *b2, *ctxb;
    cudaGetSymbolAddress((void**)&xn,   g_xn);
    cudaGetSymbolAddress((void**)&b1,   g_b1);
    cudaGetSymbolAddress((void**)&b2,   g_b2);
    cudaGetSymbolAddress((void**)&ctxb, g_ctx);

    // 1. channel layernorm
    ln_kernel<<<256, 256>>>(fmap, gn, xn);

    // 2. qkv 1x1 convs (tf32 tensor-core GEMMs)
    dim3 gg(NPIX / GBN, 256 / GBM, BATCH);
    gemm_tf32<<<gg, 256>>>(wq1, xn, b1,                    256L * NPIX, 768L * NPIX);
    gemm_tf32<<<gg, 256>>>(wk1, xn, b1 + 256L * NPIX,      256L * NPIX, 768L * NPIX);
    gemm_tf32<<<gg, 256>>>(wv1, xn, b1 + 512L * NPIX,      256L * NPIX, 768L * NPIX);

    // 3. depthwise 3x3 convs
    dwconv_kernel<<<BATCH * 768, 256>>>(b1, wq_dw, wk_dw, wv_dw, b2);

    // 4. q softmax (feature dim) * scale   5. k softmax (sequence dim)
    softmax_q_kernel<<<2048, 256>>>(b2);
    softmax_k_kernel<<<4096, 256>>>(b2);

    // 6. ctx = k^T v per (b,h)
    ctx_kernel<<<BATCH * HEADS, 256>>>(b2, ctxb);

    // 7. out = q @ ctx, + SiLU  (into xn, which is free now)
    attn_out_kernel<<<2048, 256>>>(b2, ctxb, xn);

    // 8. output 1x1 conv (y into b1, free now)
    gemm_tf32<<<gg, 256>>>(wo, xn, b1, 256L * NPIX, 256L * NPIX);

    // 9. final channel layernorm -> d_out
    ln_kernel<<<256, 256>>>(b1, gout, out);
}